// round 6
// baseline (speedup 1.0000x reference)
#include <cuda_runtime.h>
#include <cstdint>

// FerroelectricBasisConv2d — GB300 sm_103a, round 6
// g = tanh(5x+5Ec) via 2048-entry smem nearest-neighbor table (no MUFU),
// outer tanh via MUFU. u = k*x + 0.9kEc + 0.1kEc*g.
// Per term: 1 MUFU + 4 FMA + 4 ALU + 3 LDS  (was 2 MUFU @10.7 = floor 34.7us)

#define CIN     16
#define COUT    32
#define HW      32
#define NT      432          // CIN * 3 * 9
#define TILE_H  8
#define TILE_W  16
#define RG_H    10
#define RG_W    18
#define THREADS 128

#define TABN    2048
#define TAB_H   0.00439453125f          // 9/2048 (exact)
#define S5      1137.7777777777778f     // 5 * 2048/9  (index units per x)
#define SEC     1137.7777777777778f     // 2048/9 * 5  (index units per Ec)
#define CBASE   12583936.0f             // 4.5*(2048/9) + 1.5*2^23 = 1024 + 12582912
#define MLO     12582912.0f
#define MHI     12584959.0f             // MLO + 2047

__device__ __forceinline__ float tanh_fast(float x) {
    float r; asm("tanh.approx.f32 %0, %1;" : "=f"(r) : "f"(x)); return r;
}

__global__ __launch_bounds__(THREADS, 7)
void ferro_kernel(const float* __restrict__ x,
                  const float* __restrict__ k,
                  const float* __restrict__ Ec,
                  const float* __restrict__ Ps,
                  const float* __restrict__ bias,
                  const float* __restrict__ coef,
                  const float* __restrict__ out_bias,
                  float* __restrict__ out)
{
    __shared__ float  tab[TABN];              // tanh(a), a = -4.5 + i*TAB_H
    __shared__ float4 pk[NT];                 // {C_idx, k, 0.9kEc, 0.1kEc}
    __shared__ float  pw[NT];                 // Ps*coef
    __shared__ float  xs[CIN * RG_H * RG_W];  // x tile with halo
    __shared__ float  red[THREADS];

    const int tid = threadIdx.x;
    const int bx  = blockIdx.x;
    const int sub = bx & 7;
    const int sy  = sub >> 1, sx = sub & 1;
    const int co  = (bx >> 3) & 31;
    const int b   = bx >> 8;
    const int oy0 = sy * TILE_H, ox0 = sx * TILE_W;

    // ---- build gate table (tanh.approx err ~1e-6 in-distribution) ----
    #pragma unroll
    for (int i = tid; i < TABN; i += THREADS)
        tab[i] = tanh_fast(fmaf((float)i, TAB_H, -4.5f));

    // ---- stage + transform params for this co ----
    const float* kp  = k    + co * NT;
    const float* ep  = Ec   + co * NT;
    const float* pp  = Ps   + co * NT;
    const float* bp  = bias + co * NT;
    const float* cp  = coef + co * NT;
    float part = 0.0f;
    for (int j = tid; j < NT; j += THREADS) {
        float kv = kp[j], ev = ep[j], pv = pp[j], bv = bp[j], cv = cp[j];
        float ke = kv * ev;
        float Cj = fmaf(SEC, ev, CBASE);      // index const: S*(5Ec+4.5)+M
        pk[j] = make_float4(Cj, kv, 0.9f * ke, 0.1f * ke);
        pw[j] = pv * cv;
        part += bv * cv;
    }
    red[tid] = part;

    // ---- stage x tile (zero-padded halo) ----
    for (int i = tid; i < CIN * RG_H * RG_W; i += THREADS) {
        int cin = i / (RG_H * RG_W);
        int rem = i - cin * (RG_H * RG_W);
        int r   = rem / RG_W;
        int c   = rem - r * RG_W;
        int gy  = oy0 - 1 + r;
        int gx  = ox0 - 1 + c;
        float v = 0.0f;
        if ((unsigned)gy < (unsigned)HW && (unsigned)gx < (unsigned)HW)
            v = x[((b * CIN + cin) * HW + gy) * HW + gx];
        xs[i] = v;
    }
    __syncthreads();

    #pragma unroll
    for (int s = THREADS / 2; s > 0; s >>= 1) {
        if (tid < s) red[tid] += red[tid + s];
        __syncthreads();
    }

    const int ty = tid >> 4;
    const int tx = tid & 15;

    float acc = red[0] + __ldg(out_bias + co);

    for (int cin = 0; cin < CIN; ++cin) {
        const float* xb = xs + cin * (RG_H * RG_W) + ty * RG_W + tx;
        const int jb = cin * 27;
        #pragma unroll
        for (int kh = 0; kh < 3; ++kh) {
            #pragma unroll
            for (int kw = 0; kw < 3; ++kw) {
                const float xv  = xb[kh * RG_W + kw];
                const int   tap = kh * 3 + kw;
                #pragma unroll
                for (int kkk = 0; kkk < 3; ++kkk) {
                    const int j = jb + kkk * 9 + tap;
                    float4 p = pk[j];
                    float  w = pw[j];
                    // gate via table: t = M + round(index), nearest entry
                    float tf = fmaf(xv, S5, p.x);
                    tf = fminf(fmaxf(tf, MLO), MHI);
                    int idx = (int)(__float_as_uint(tf) & 0x7FFu);
                    float g = tab[idx];
                    float base = fmaf(p.y, xv, p.z);      // k*x + 0.9kEc
                    float u = fmaf(p.w, g, base);         // + 0.1kEc*g
                    float t = tanh_fast(u);
                    acc = fmaf(w, t, acc);
                }
            }
        }
    }

    const int oy = oy0 + ty, ox = ox0 + tx;
    out[((b * COUT + co) * HW + oy) * HW + ox] = acc;
}

extern "C" void kernel_launch(void* const* d_in, const int* in_sizes, int n_in,
                              void* d_out, int out_size)
{
    const float* x        = (const float*)d_in[0];
    const float* k        = (const float*)d_in[1];
    const float* Ec       = (const float*)d_in[2];
    const float* Ps       = (const float*)d_in[3];
    const float* bias     = (const float*)d_in[4];
    const float* coef     = (const float*)d_in[5];
    const float* out_bias = (const float*)d_in[6];
    float* out = (float*)d_out;

    ferro_kernel<<<4 * 32 * 8, THREADS>>>(x, k, Ec, Ps, bias, coef, out_bias, out);
}

// round 7
// speedup vs baseline: 1.1739x; 1.1739x over previous
#include <cuda_runtime.h>
#include <cuda_fp16.h>
#include <cstdint>

// FerroelectricBasisConv2d — GB300 sm_103a, round 7
//   g = tanh(5x + 5Ec)    <- PACKED: tanh.approx.f16x2, pairing cin c with c+8
//   u = k*x + 0.9kEc + 0.1kEc*g
//   out = sum( Ps*coef * tanh(u) ) + sum(bias*coef) + out_bias   (outer tanh fp32 MUFU)
// MUFU/term: 16.05 cyc (was 21.4 = round-4 floor 34.7us)

#define CIN     16
#define COUT    32
#define HW      32
#define NT      432          // CIN * 3 * 9
#define NPAIR   216          // pair (cin c, cin c+8), same tap/kkk
#define TILE_H  8
#define TILE_W  16
#define RG_H    10
#define RG_W    18
#define THREADS 128

__device__ __forceinline__ float tanh_fast(float x) {
    float r; asm("tanh.approx.f32 %0, %1;" : "=f"(r) : "f"(x)); return r;
}
__device__ __forceinline__ __half2 tanh2_fast(__half2 x) {
    uint32_t xi = *reinterpret_cast<uint32_t*>(&x), ri;
    asm("tanh.approx.f16x2 %0, %1;" : "=r"(ri) : "r"(xi));
    return *reinterpret_cast<__half2*>(&ri);
}

__global__ __launch_bounds__(THREADS, 7)
void ferro_kernel(const float* __restrict__ x,
                  const float* __restrict__ k,
                  const float* __restrict__ Ec,
                  const float* __restrict__ Ps,
                  const float* __restrict__ bias,
                  const float* __restrict__ coef,
                  const float* __restrict__ out_bias,
                  float* __restrict__ out)
{
    __shared__ float4  pk[NT];                 // {k, 0.9kEc, 0.1kEc, Ps*coef}, j = cin*27 + kkk*9 + tap
    __shared__ __half2 ec2h[NPAIR];            // {5Ec[j], 5Ec[j+216]} for j < 216 (cin < 8)
    __shared__ float   xs[CIN * RG_H * RG_W];  // x tile with halo
    __shared__ float   red[THREADS];

    const int tid = threadIdx.x;
    const int bx  = blockIdx.x;
    const int sub = bx & 7;
    const int sy  = sub >> 1, sx = sub & 1;
    const int co  = (bx >> 3) & 31;
    const int b   = bx >> 8;
    const int oy0 = sy * TILE_H, ox0 = sx * TILE_W;

    // ---- stage + transform params for this co ----
    const float* kp  = k    + co * NT;
    const float* ep  = Ec   + co * NT;
    const float* pp  = Ps   + co * NT;
    const float* bp  = bias + co * NT;
    const float* cp  = coef + co * NT;
    float part = 0.0f;
    for (int j = tid; j < NT; j += THREADS) {
        float kv = kp[j], ev = ep[j], pv = pp[j], bv = bp[j], cv = cp[j];
        float ke = kv * ev;
        pk[j] = make_float4(kv, 0.9f * ke, 0.1f * ke, pv * cv);
        part += bv * cv;
    }
    for (int j = tid; j < NPAIR; j += THREADS)
        ec2h[j] = __floats2half2_rn(5.0f * ep[j], 5.0f * ep[j + NPAIR]);
    red[tid] = part;

    // ---- stage x tile (zero-padded halo) ----
    for (int i = tid; i < CIN * RG_H * RG_W; i += THREADS) {
        int cin = i / (RG_H * RG_W);
        int rem = i - cin * (RG_H * RG_W);
        int r   = rem / RG_W;
        int c   = rem - r * RG_W;
        int gy  = oy0 - 1 + r;
        int gx  = ox0 - 1 + c;
        float v = 0.0f;
        if ((unsigned)gy < (unsigned)HW && (unsigned)gx < (unsigned)HW)
            v = x[((b * CIN + cin) * HW + gy) * HW + gx];
        xs[i] = v;
    }
    __syncthreads();

    #pragma unroll
    for (int s = THREADS / 2; s > 0; s >>= 1) {
        if (tid < s) red[tid] += red[tid + s];
        __syncthreads();
    }

    const int ty = tid >> 4;
    const int tx = tid & 15;

    float acc0 = red[0] + __ldg(out_bias + co);
    float acc1 = 0.0f;
    const __half2 FIVE2 = __floats2half2_rn(5.0f, 5.0f);

    for (int c = 0; c < 8; ++c) {
        const float* xb0 = xs + c       * (RG_H * RG_W) + ty * RG_W + tx;
        const float* xb1 = xs + (c + 8) * (RG_H * RG_W) + ty * RG_W + tx;
        const int jb = c * 27;                 // pair j in [0,216): cin c; partner j+216: cin c+8
        #pragma unroll
        for (int kh = 0; kh < 3; ++kh) {
            #pragma unroll
            for (int kw = 0; kw < 3; ++kw) {
                const float xv0 = xb0[kh * RG_W + kw];
                const float xv1 = xb1[kh * RG_W + kw];
                const __half2 xv2 = __floats2half2_rn(xv0, xv1);
                const int tap = kh * 3 + kw;
                #pragma unroll
                for (int kkk = 0; kkk < 3; ++kkk) {
                    const int j0 = jb + kkk * 9 + tap;      // < 216
                    const int j1 = j0 + NPAIR;
                    // packed gate: {tanh(5x0+5Ec_j0), tanh(5x1+5Ec_j1)}
                    __half2 a2 = __hfma2(FIVE2, xv2, ec2h[j0]);
                    __half2 g2 = tanh2_fast(a2);
                    float g0 = __low2float(g2);
                    float g1 = __high2float(g2);
                    float4 p0 = pk[j0];
                    float4 p1 = pk[j1];
                    float u0 = fmaf(p0.z, g0, fmaf(p0.x, xv0, p0.y));
                    float u1 = fmaf(p1.z, g1, fmaf(p1.x, xv1, p1.y));
                    float t0 = tanh_fast(u0);
                    float t1 = tanh_fast(u1);
                    acc0 = fmaf(p0.w, t0, acc0);
                    acc1 = fmaf(p1.w, t1, acc1);
                }
            }
        }
    }

    const int oy = oy0 + ty, ox = ox0 + tx;
    out[((b * COUT + co) * HW + oy) * HW + ox] = acc0 + acc1;
}

extern "C" void kernel_launch(void* const* d_in, const int* in_sizes, int n_in,
                              void* d_out, int out_size)
{
    const float* x        = (const float*)d_in[0];
    const float* k        = (const float*)d_in[1];
    const float* Ec       = (const float*)d_in[2];
    const float* Ps       = (const float*)d_in[3];
    const float* bias     = (const float*)d_in[4];
    const float* coef     = (const float*)d_in[5];
    const float* out_bias = (const float*)d_in[6];
    float* out = (float*)d_out;

    ferro_kernel<<<4 * 32 * 8, THREADS>>>(x, k, Ec, Ps, bias, coef, out_bias, out);
}